// round 3
// baseline (speedup 1.0000x reference)
#include <cuda_runtime.h>
#include <cuda_bf16.h>
#include <math_constants.h>

#define NN 50000
#define NE 800000
#define HID 64
#define FULL 0xffffffffu

// ---------------------------------------------------------------------------
// Scratch (device globals; allocation-free per harness rules)
// ---------------------------------------------------------------------------
__device__ __align__(16) float    g_m0  [NN * HID];   // n @ W1_rel[0]
__device__ __align__(16) float    g_m1  [NN * HID];   // n @ W1_rel[1]
__device__ __align__(16) float    g_r1  [NN * HID];   // n @ W1_root + b1
__device__ __align__(16) float    g_hpre[NN * HID];   // pre-relu h (conv1 out)
__device__ __align__(16) float    g_p0  [NN * HID];   // h @ W2_rel[0]
__device__ __align__(16) float    g_p1  [NN * HID];   // h @ W2_rel[1]
__device__ __align__(16) float    g_r2  [NN * HID];   // h @ W2_root + b2
// CSR by dst
__device__ int      g_deg[NN];
__device__ int      g_off[NN + 1];
__device__ int      g_cur[NN];
__device__ unsigned g_csr_pk[NE];                     // src | (typ<<31)
__device__ __align__(8) float2 g_csr_ea[NE];          // edge_attr in CSR order

// ---------------------------------------------------------------------------
// f32x2 packed-FMA helpers (sm_100+ PTX; FFMA2 unreachable from plain C++)
// ---------------------------------------------------------------------------
__device__ __forceinline__ unsigned long long pack_dup(float v) {
    unsigned long long r;
    asm("mov.b64 %0, {%1, %1};" : "=l"(r) : "r"(__float_as_uint(v)));
    return r;
}
__device__ __forceinline__ unsigned long long pack2(float lo, float hi) {
    unsigned long long r;
    asm("mov.b64 %0, {%1, %2};" : "=l"(r) : "r"(__float_as_uint(lo)), "r"(__float_as_uint(hi)));
    return r;
}
__device__ __forceinline__ unsigned long long fma2(unsigned long long a,
                                                   unsigned long long b,
                                                   unsigned long long c) {
    unsigned long long d;
    asm("fma.rn.f32x2 %0, %1, %2, %3;" : "=l"(d) : "l"(a), "l"(b), "l"(c));
    return d;
}
__device__ __forceinline__ unsigned long long add2(unsigned long long a,
                                                   unsigned long long b) {
    unsigned long long d;
    asm("add.rn.f32x2 %0, %1, %2;" : "=l"(d) : "l"(a), "l"(b));
    return d;
}

// ---------------------------------------------------------------------------
// CSR build: histogram, block-wide scan (1 block), fill
// ---------------------------------------------------------------------------
__global__ void k_hist(const int* __restrict__ ei) {
    int e = blockIdx.x * blockDim.x + threadIdx.x;
    if (e < NE) atomicAdd(&g_deg[ei[NE + e]], 1);
}

__global__ void k_scan() {
    __shared__ int warpsum[32];
    int tid  = threadIdx.x;
    int lane = tid & 31;
    int wid  = tid >> 5;
    int carry = 0;
    for (int base = 0; base < NN; base += 1024) {
        int i = base + tid;
        int v = (i < NN) ? g_deg[i] : 0;
        int s = v;
        #pragma unroll
        for (int o = 1; o < 32; o <<= 1) {
            int t = __shfl_up_sync(FULL, s, o);
            if (lane >= o) s += t;
        }
        if (lane == 31) warpsum[wid] = s;
        __syncthreads();
        if (wid == 0) {
            int ws = warpsum[lane];
            #pragma unroll
            for (int o = 1; o < 32; o <<= 1) {
                int t = __shfl_up_sync(FULL, ws, o);
                if (lane >= o) ws += t;
            }
            warpsum[lane] = ws;
        }
        __syncthreads();
        int wpre = (wid > 0) ? warpsum[wid - 1] : 0;
        int excl = carry + wpre + s - v;
        if (i < NN) { g_off[i] = excl; g_cur[i] = excl; }
        int total = warpsum[31];
        __syncthreads();
        carry += total;
    }
    if (tid == 0) g_off[NN] = NE;
}

__global__ void k_fill(const int* __restrict__ ei,
                       const float* __restrict__ ea,
                       const int* __restrict__ et) {
    int e = blockIdx.x * blockDim.x + threadIdx.x;
    if (e >= NE) return;
    int dst = ei[NE + e];
    int pos = atomicAdd(&g_cur[dst], 1);
    g_csr_pk[pos] = (unsigned)ei[e] | ((unsigned)et[e] << 31);
    g_csr_ea[pos] = ((const float2*)ea)[e];
}

// ---------------------------------------------------------------------------
// Fused triple GEMM with packed f32x2 FMA:
//   out{0,1,2}[N,64] = f(in)[N,64] @ {W0,W1,W2}  (+bias on W2)
// mode 0: f(in) = relu(x@Wn+bn) fused;  mode 1: f(in) = relu(in)
// 256 threads, 64 nodes/block; thread: 4 nodes x (2 col-pairs) x 3 matrices.
// ---------------------------------------------------------------------------
#define NPB 64
#define INPAD 68
extern __shared__ float s_dyn[];
__global__ __launch_bounds__(256)
void k_gemm3(const float* __restrict__ in,
             const float* __restrict__ W0,
             const float* __restrict__ W1,
             const float* __restrict__ W2,
             const float* __restrict__ bias2,
             const float* __restrict__ Wn,
             const float* __restrict__ bn,
             float* __restrict__ o0,
             float* __restrict__ o1,
             float* __restrict__ o2,
             int mode) {
    float* sW  = s_dyn;                 // 3 * 64 * 64
    float* sIn = s_dyn + 3 * 4096;      // 64 * INPAD
    __shared__ float sX[NPB * 3];
    int tid = threadIdx.x;
    int nbase = blockIdx.x * NPB;

    for (int i = tid * 4; i < 4096; i += 1024) {
        *(float4*)&sW[i]        = *(const float4*)&W0[i];
        *(float4*)&sW[4096 + i] = *(const float4*)&W1[i];
        *(float4*)&sW[8192 + i] = *(const float4*)&W2[i];
    }

    if (mode == 0) {
        if (tid < NPB * 3) {
            int nd = tid / 3, c = tid % 3;
            int node = nbase + nd;
            sX[tid] = (node < NN) ? __ldg(&in[node * 3 + c]) : 0.f;
        }
        __syncthreads();
        for (int i = tid; i < NPB * 64; i += 256) {
            int nd = i >> 6, k = i & 63;
            float v = fmaf(sX[nd * 3 + 0], __ldg(&Wn[k]),
                      fmaf(sX[nd * 3 + 1], __ldg(&Wn[64 + k]),
                      fmaf(sX[nd * 3 + 2], __ldg(&Wn[128 + k]), __ldg(&bn[k]))));
            sIn[nd * INPAD + k] = fmaxf(v, 0.f);
        }
    } else {
        for (int i = tid * 4; i < NPB * 64; i += 1024) {
            int nd = i >> 6, k = i & 63;
            int node = nbase + nd;
            float4 v = make_float4(0.f, 0.f, 0.f, 0.f);
            if (node < NN) v = *(const float4*)&in[node * 64 + k];
            v.x = fmaxf(v.x, 0.f); v.y = fmaxf(v.y, 0.f);
            v.z = fmaxf(v.z, 0.f); v.w = fmaxf(v.w, 0.f);
            *(float4*)&sIn[nd * INPAD + k] = v;
        }
    }
    __syncthreads();

    int tx = tid & 15, ty = tid >> 4;
    int c0 = tx * 4, n0 = ty * 4;

    unsigned long long acc[3][4][2];
    #pragma unroll
    for (int m = 0; m < 3; m++)
        #pragma unroll
        for (int j = 0; j < 4; j++) { acc[m][j][0] = 0ull; acc[m][j][1] = 0ull; }

    #pragma unroll 2
    for (int k = 0; k < 64; k++) {
        // each ulonglong2 = one float4 of W = 2 packed f32x2 col-pairs
        ulonglong2 w0 = *(const ulonglong2*)&sW[k * 64 + c0];
        ulonglong2 w1 = *(const ulonglong2*)&sW[4096 + k * 64 + c0];
        ulonglong2 w2 = *(const ulonglong2*)&sW[8192 + k * 64 + c0];
        unsigned long long a2[4];
        #pragma unroll
        for (int j = 0; j < 4; j++) a2[j] = pack_dup(sIn[(n0 + j) * INPAD + k]);
        #pragma unroll
        for (int j = 0; j < 4; j++) {
            acc[0][j][0] = fma2(a2[j], w0.x, acc[0][j][0]);
            acc[0][j][1] = fma2(a2[j], w0.y, acc[0][j][1]);
            acc[1][j][0] = fma2(a2[j], w1.x, acc[1][j][0]);
            acc[1][j][1] = fma2(a2[j], w1.y, acc[1][j][1]);
            acc[2][j][0] = fma2(a2[j], w2.x, acc[2][j][0]);
            acc[2][j][1] = fma2(a2[j], w2.y, acc[2][j][1]);
        }
    }

    float4 bv = *(const float4*)&bias2[c0];
    unsigned long long bb0 = pack2(bv.x, bv.y);
    unsigned long long bb1 = pack2(bv.z, bv.w);

    #pragma unroll
    for (int j = 0; j < 4; j++) {
        int node = nbase + n0 + j;
        if (node >= NN) break;
        *(ulonglong2*)&o0[node * 64 + c0] = make_ulonglong2(acc[0][j][0], acc[0][j][1]);
        *(ulonglong2*)&o1[node * 64 + c0] = make_ulonglong2(acc[1][j][0], acc[1][j][1]);
        *(ulonglong2*)&o2[node * 64 + c0] =
            make_ulonglong2(add2(acc[2][j][0], bb0), add2(acc[2][j][1], bb1));
    }
}

// ---------------------------------------------------------------------------
// conv1 gather: one warp per dst node; 2-edge unroll for MLP.
//   msum  = sum_e m_{typ}[src]          (lane owns cols 2l, 2l+1)
//   aggev = sum_e relu(ea@We+be)        (lane owns dim l of 32)
//   hpre  = r1 + msum + aggev @ W1_edge
// ---------------------------------------------------------------------------
__global__ void k_gather1(const float* __restrict__ We,
                          const float* __restrict__ be,
                          const float* __restrict__ W1e) {
    __shared__ float  sWe0[32], sWe1[32], sbe[32];
    __shared__ float2 sW1e[32 * 32];
    int tid = threadIdx.x;
    if (tid < 32) { sWe0[tid] = We[tid]; sWe1[tid] = We[32 + tid]; sbe[tid] = be[tid]; }
    for (int i = tid; i < 1024; i += blockDim.x)
        sW1e[i] = ((const float2*)W1e)[i];
    __syncthreads();

    int lane = tid & 31;
    int node = (blockIdx.x * blockDim.x + tid) >> 5;
    if (node >= NN) return;
    int s0 = g_off[node], s1 = g_off[node + 1];

    float  ev = 0.f;
    float2 ms = make_float2(0.f, 0.f);
    int e = s0;
    for (; e + 2 <= s1; e += 2) {
        unsigned pkA = __ldg(&g_csr_pk[e]);
        unsigned pkB = __ldg(&g_csr_pk[e + 1]);
        float2 aA = __ldg(&g_csr_ea[e]);
        float2 aB = __ldg(&g_csr_ea[e + 1]);
        const float2* mA = (pkA >> 31) ? (const float2*)g_m1 : (const float2*)g_m0;
        const float2* mB = (pkB >> 31) ? (const float2*)g_m1 : (const float2*)g_m0;
        float2 vA = __ldg(&mA[(pkA & 0x7FFFFFFFu) * 32 + lane]);
        float2 vB = __ldg(&mB[(pkB & 0x7FFFFFFFu) * 32 + lane]);
        ev += fmaxf(fmaf(aA.x, sWe0[lane], fmaf(aA.y, sWe1[lane], sbe[lane])), 0.f);
        ev += fmaxf(fmaf(aB.x, sWe0[lane], fmaf(aB.y, sWe1[lane], sbe[lane])), 0.f);
        ms.x += vA.x + vB.x;
        ms.y += vA.y + vB.y;
    }
    if (e < s1) {
        unsigned pk = __ldg(&g_csr_pk[e]);
        float2 a = __ldg(&g_csr_ea[e]);
        ev += fmaxf(fmaf(a.x, sWe0[lane], fmaf(a.y, sWe1[lane], sbe[lane])), 0.f);
        const float2* m = (pk >> 31) ? (const float2*)g_m1 : (const float2*)g_m0;
        float2 v = __ldg(&m[(pk & 0x7FFFFFFFu) * 32 + lane]);
        ms.x += v.x; ms.y += v.y;
    }

    float2 acc = make_float2(0.f, 0.f);
    #pragma unroll
    for (int k = 0; k < 32; k++) {
        float ek = __shfl_sync(FULL, ev, k);
        float2 w = sW1e[k * 32 + lane];
        acc.x = fmaf(ek, w.x, acc.x);
        acc.y = fmaf(ek, w.y, acc.y);
    }
    float2 r = *(const float2*)&g_r1[node * 64 + 2 * lane];
    *(float2*)&g_hpre[node * 64 + 2 * lane] =
        make_float2(r.x + ms.x + acc.x, r.y + ms.y + acc.y);
}

// ---------------------------------------------------------------------------
// conv2 gather + readout: one warp per dst node; 2-edge unroll.
//   mx = max_e p_{typ}[src] (0 for empty); h2 = relu(mx + r2)
//   out = tanh(h2 @ Wc + bc) * 5
// ---------------------------------------------------------------------------
__global__ void k_gather2(const float* __restrict__ Wc,
                          const float* __restrict__ bc,
                          float* __restrict__ out) {
    int tid  = threadIdx.x;
    int lane = tid & 31;
    int node = (blockIdx.x * blockDim.x + tid) >> 5;
    if (node >= NN) return;
    int s0 = g_off[node], s1 = g_off[node + 1];

    float2 mx = make_float2(-CUDART_INF_F, -CUDART_INF_F);
    int e = s0;
    for (; e + 2 <= s1; e += 2) {
        unsigned pkA = __ldg(&g_csr_pk[e]);
        unsigned pkB = __ldg(&g_csr_pk[e + 1]);
        const float2* pA = (pkA >> 31) ? (const float2*)g_p1 : (const float2*)g_p0;
        const float2* pB = (pkB >> 31) ? (const float2*)g_p1 : (const float2*)g_p0;
        float2 vA = __ldg(&pA[(pkA & 0x7FFFFFFFu) * 32 + lane]);
        float2 vB = __ldg(&pB[(pkB & 0x7FFFFFFFu) * 32 + lane]);
        mx.x = fmaxf(mx.x, fmaxf(vA.x, vB.x));
        mx.y = fmaxf(mx.y, fmaxf(vA.y, vB.y));
    }
    if (e < s1) {
        unsigned pk = __ldg(&g_csr_pk[e]);
        const float2* p = (pk >> 31) ? (const float2*)g_p1 : (const float2*)g_p0;
        float2 v = __ldg(&p[(pk & 0x7FFFFFFFu) * 32 + lane]);
        mx.x = fmaxf(mx.x, v.x);
        mx.y = fmaxf(mx.y, v.y);
    }
    if (s1 == s0) mx = make_float2(0.f, 0.f);

    float2 r = *(const float2*)&g_r2[node * 64 + 2 * lane];
    float h0 = fmaxf(mx.x + r.x, 0.f);
    float h1 = fmaxf(mx.y + r.y, 0.f);
    float p = fmaf(h0, __ldg(&Wc[2 * lane]), h1 * __ldg(&Wc[2 * lane + 1]));
    #pragma unroll
    for (int o = 16; o > 0; o >>= 1) p += __shfl_xor_sync(FULL, p, o);
    if (lane == 0) out[node] = tanhf(p + __ldg(bc)) * 5.0f;
}

// ---------------------------------------------------------------------------
// launch
// ---------------------------------------------------------------------------
extern "C" void kernel_launch(void* const* d_in, const int* in_sizes, int n_in,
                              void* d_out, int out_size) {
    const float* x      = (const float*)d_in[0];
    const int*   ei     = (const int*)  d_in[1];
    const float* ea     = (const float*)d_in[2];
    const int*   et     = (const int*)  d_in[3];
    const float* Wn     = (const float*)d_in[4];
    const float* bn     = (const float*)d_in[5];
    const float* We     = (const float*)d_in[6];
    const float* be     = (const float*)d_in[7];
    const float* W1_rel = (const float*)d_in[8];
    const float* W1_edge= (const float*)d_in[9];
    const float* W1_root= (const float*)d_in[10];
    const float* b1     = (const float*)d_in[11];
    const float* W2_rel = (const float*)d_in[12];
    const float* W2_root= (const float*)d_in[13];
    const float* b2     = (const float*)d_in[14];
    const float* Wc     = (const float*)d_in[15];
    const float* bc     = (const float*)d_in[16];
    float* out          = (float*)d_out;

    float *pm0, *pm1, *pr1, *phpre, *pp0, *pp1, *pr2;
    int* pdeg;
    cudaGetSymbolAddress((void**)&pm0,   g_m0);
    cudaGetSymbolAddress((void**)&pm1,   g_m1);
    cudaGetSymbolAddress((void**)&pr1,   g_r1);
    cudaGetSymbolAddress((void**)&phpre, g_hpre);
    cudaGetSymbolAddress((void**)&pp0,   g_p0);
    cudaGetSymbolAddress((void**)&pp1,   g_p1);
    cudaGetSymbolAddress((void**)&pr2,   g_r2);
    cudaGetSymbolAddress((void**)&pdeg,  g_deg);

    static const int SMEM = (3 * 4096 + NPB * INPAD) * sizeof(float);
    cudaFuncSetAttribute(k_gemm3, cudaFuncAttributeMaxDynamicSharedMemorySize, SMEM);

    const int gemmBlocks = (NN + NPB - 1) / NPB;
    const int edgeBlocks = (NE + 255) / 256;
    const int nodeWarpBlocks = (NN * 32 + 255) / 256;

    // CSR build (shared by both convs)
    cudaMemsetAsync(pdeg, 0, NN * sizeof(int));
    k_hist<<<edgeBlocks, 256>>>(ei);
    k_scan<<<1, 1024>>>();
    k_fill<<<edgeBlocks, 256>>>(ei, ea, et);

    // conv1 node-side: n = relu(x@Wn+bn) fused; m0, m1, r1
    k_gemm3<<<gemmBlocks, 256, SMEM>>>(x, W1_rel, W1_rel + 4096, W1_root, b1,
                                       Wn, bn, pm0, pm1, pr1, 0);
    // conv1 gather (sum) + edge-feature fold
    k_gather1<<<nodeWarpBlocks, 256>>>(We, be, W1_edge);

    // conv2 node-side: h = relu(hpre) fused; p0, p1, r2
    k_gemm3<<<gemmBlocks, 256, SMEM>>>(phpre, W2_rel, W2_rel + 4096, W2_root, b2,
                                       nullptr, nullptr, pp0, pp1, pr2, 1);
    // conv2 gather (max) + readout fused
    k_gather2<<<nodeWarpBlocks, 256>>>(Wc, bc, out);
}